// round 6
// baseline (speedup 1.0000x reference)
#include <cuda_runtime.h>
#include <cuda_bf16.h>

#define NN      16384
#define GRID    64
#define THREADS 1024
#define CAP     512          // per-bucket capacity (mean 256, sd 16)
#define NBK     64           // rank buckets (rank >> 8)
#define NCROSS  2016         // C(64,2) cross-bucket tiles
#define NDIAG   128          // 64 buckets x 2 half-tiles
#define NTASK   (NCROSS + NDIAG)
#define NSUB    256          // 64 blocks x 4 sub-tiles
#define ITERS   ((NTASK + NSUB - 1) / NSUB)   // 9

// ---------------- device scratch ----------------
__device__ __align__(16) float     g_bsc[NBK * CAP];  // bucket scores (arrival order)
__device__ __align__(16) int       g_brk[NBK * CAP];  // bucket ranks
__device__ __align__(16) float     g_bso[NBK * CAP];  // bucket scores value-sorted asc (pad +MAX)
__device__ __align__(16) float     g_bss[NBK * CAP];  // suffix sums of sorted (pad 0)
__device__ int                     g_bcnt[NBK];
__device__ int                     g_is32f;           // 1 if ranks buffer is int32
__device__ double                  g_part[GRID];
__device__ long long               g_tied[GRID];
__device__ unsigned                g_barc;            // grid barrier ticket counter

// Replay-safe grid barrier: monotonic counter, generation = ticket/GRID.
// Each launch performs 4 barriers -> +256 arrivals, counter stays = 0 mod GRID.
__device__ __forceinline__ void gbar(int tid) {
    __threadfence();
    __syncthreads();
    if (tid == 0) {
        unsigned t = atomicAdd(&g_barc, 1u);
        unsigned target = (t / GRID + 1u) * GRID;
        while (*(volatile unsigned*)&g_barc < target) { }
    }
    __syncthreads();
}

extern "C" __global__ void __launch_bounds__(THREADS, 1)
k_all(const float* __restrict__ scores, const unsigned int* __restrict__ rw,
      float* __restrict__ out)
{
    const int tid = threadIdx.x;
    const int b   = blockIdx.x;

    __shared__ float sc[4][CAP];     // per-half col data (sorted scores / diag scores)
    __shared__ float sm[4][CAP];     // per-half suffix sums (cross) ; unused in diag
    __shared__ int   srk[4][CAP];    // per-half diag ranks
    __shared__ double wacc[32];
    __shared__ long long wtt[32];
    __shared__ int s_is32;

    // ---------- P0: zero bucket counters + dtype detect ----------
    // int64 (LE): odd 32-bit words of first 64KB are high halves of values
    // < 2^15 -> all zero.  int32: odd words are actual rank values.
    if (b == 0) {
        int found = 0;
#pragma unroll
        for (int u = 0; u < 8; u++) {
            int idx = tid * 8 + u;                 // < 8192, word 2*idx+1 <= 16383
            found |= (rw[2 * idx + 1] != 0u);
        }
        int any = __syncthreads_or(found);
        if (tid == 0) g_is32f = any;
    } else if (b == 1) {
        if (tid < NBK) g_bcnt[tid] = 0;
    }
    gbar(tid);

    // ---------- P1: bucket scatter ----------
    if (tid == 0) s_is32 = __ldcg(&g_is32f);
    __syncthreads();
    {
        int i = b * THREADS + tid;
        if (i < NN) {
            int r = (int)rw[s_is32 ? i : 2 * i];
            if ((unsigned)r >= (unsigned)NN) r = 0;     // defensive: never IMA
            int k = r >> 8;
            int pos = atomicAdd(&g_bcnt[k], 1);
            if (pos < CAP) {
                g_bsc[k * CAP + pos] = scores[i];
                g_brk[k * CAP + pos] = r;
            }
        }
    }
    gbar(tid);

    // ---------- P2: block b sorts bucket b (bitonic 512) + suffix sums ----------
    {
        int cnt = min(__ldcg(&g_bcnt[b]), CAP);
        float* v  = sc[0];
        float* ss = sm[0];
        if (tid < CAP) v[tid] = (tid < cnt) ? __ldcg(&g_bsc[b * CAP + tid]) : 3.402823e38f;
        __syncthreads();
        for (int k = 2; k <= CAP; k <<= 1)
            for (int j = k >> 1; j > 0; j >>= 1) {
                if (tid < CAP) {
                    int ixj = tid ^ j;
                    if (ixj > tid) {
                        float x = v[tid], y = v[ixj];
                        bool up = ((tid & k) == 0);
                        if ((x > y) == up) { v[tid] = y; v[ixj] = x; }
                    }
                }
                __syncthreads();
            }
        if (tid < CAP) ss[tid] = (tid < cnt) ? v[tid] : 0.0f;
        __syncthreads();
        for (int off = 1; off < CAP; off <<= 1) {
            float add = 0.0f;
            if (tid < CAP && tid + off < CAP) add = ss[tid + off];
            __syncthreads();
            if (tid < CAP) ss[tid] += add;
            __syncthreads();
        }
        if (tid < CAP) {
            g_bso[b * CAP + tid] = v[tid];
            g_bss[b * CAP + tid] = ss[tid];
        }
    }
    gbar(tid);

    // ---------- P3: cross tiles (analytic) + diag half-tiles (brute + ties) ----------
    const int h    = tid >> 8;       // sub-tile 0..3 within block
    const int htid = tid & 255;
    const int sub  = b * 4 + h;
    double acc = 0.0;
    long long tied = 0;

    for (int kk = 0; kk < ITERS; kk++) {
        int t = sub + kk * NSUB;
        int rB = -1, cB = -1, diagb = -1, dpart = 0;
        if (t < NCROSS) {
            // decode t -> (rB < cB) pair among 64 buckets; off(r) = r*(127-r)/2
            int r0 = (int)((127.0 - sqrt(16129.0 - 8.0 * (double)t)) * 0.5);
            if (r0 < 0) r0 = 0; if (r0 > 62) r0 = 62;
            while (r0 < 62 && (r0 + 1) * (127 - (r0 + 1)) / 2 <= t) r0++;
            while (r0 > 0 && r0 * (127 - r0) / 2 > t) r0--;
            rB = r0;
            cB = r0 + 1 + (t - r0 * (127 - r0) / 2);
            for (int u = htid; u < CAP; u += 256) {
                sc[h][u] = __ldcg(&g_bso[cB * CAP + u]);
                sm[h][u] = __ldcg(&g_bss[cB * CAP + u]);
            }
        } else if (t < NTASK) {
            int dd = t - NCROSS;
            diagb = dd >> 1;
            dpart = dd & 1;
            for (int u = htid; u < CAP; u += 256) {
                sc[h][u]  = __ldcg(&g_bsc[diagb * CAP + u]);
                srk[h][u] = __ldcg(&g_brk[diagb * CAP + u]);
            }
        }
        __syncthreads();

        if (rB >= 0) {
            int cntc = min(__ldcg(&g_bcnt[cB]), CAP);
            int cntr = min(__ldcg(&g_bcnt[rB]), CAP);
            for (int i2 = htid; i2 < cntr; i2 += 256) {
                float ap = 1.0f - __ldcg(&g_bsc[rB * CAP + i2]);
                float tv = -ap;
                int pos = 0;                       // count of sorted elems <= tv
#pragma unroll
                for (int s = 256; s > 0; s >>= 1) {
                    int np = pos + s;
                    if (np <= CAP && sc[h][np - 1] <= tv) pos = np;
                }
                float suf = (pos < CAP) ? sm[h][pos] : 0.0f;
                acc += (double)fmaf((float)(cntc - pos), ap, suf);
            }
        } else if (diagb >= 0) {
            int cnt = min(__ldcg(&g_bcnt[diagb]), CAP);
            int i2 = htid + dpart * 256;
            if (i2 < cnt) {
                float si = sc[h][i2];
                int   ri = srk[h][i2];
                float api = 1.0f - si;
                double lacc = 0.0;
                for (int j = 0; j < cnt; j++) {
                    int rj = srk[h][j];
                    if (rj > ri)                lacc += (double)fmaxf(api + sc[h][j], 0.0f);
                    else if (rj == ri && j > i2) tied++;
                }
                acc += lacc;
            }
        }
        __syncthreads();
    }

    // block reduction of acc / tied
#pragma unroll
    for (int o = 16; o; o >>= 1) {
        acc  += __shfl_down_sync(0xffffffffu, acc, o);
        tied += __shfl_down_sync(0xffffffffu, tied, o);
    }
    {
        int lane = tid & 31, wid = tid >> 5;
        if (lane == 0) { wacc[wid] = acc; wtt[wid] = tied; }
        __syncthreads();
        if (tid == 0) {
            double s = 0.0; long long tt = 0;
#pragma unroll
            for (int u = 0; u < 32; u++) { s += wacc[u]; tt += wtt[u]; }
            g_part[b] = s;
            g_tied[b] = tt;
        }
    }
    gbar(tid);

    // ---------- P4: final ----------
    if (b == 0 && tid == 0) {
        double s = 0.0; long long tt = 0;
        for (int u = 0; u < GRID; u++) {
            s  += __ldcg(&g_part[u]);
            tt += __ldcg(&g_tied[u]);
        }
        double np = (double)(134209536ll - tt);   // C(16384,2) - tied pairs
        out[0] = (np > 0.0) ? (float)(s / np) : 0.0f;
    }
}

// ---------------- launch: ONE kernel ----------------
extern "C" void kernel_launch(void* const* d_in, const int* in_sizes, int n_in,
                              void* d_out, int out_size) {
    const float*        scores = (const float*)d_in[0];
    const unsigned int* ranks  = (const unsigned int*)d_in[1];
    float* out = (float*)d_out;

    k_all<<<GRID, THREADS>>>(scores, ranks, out);
}

// round 7
// speedup vs baseline: 1.1021x; 1.1021x over previous
#include <cuda_runtime.h>
#include <cuda_bf16.h>

#define NN      16384
#define CAP     512           // per-bucket capacity (mean 256, sd 16)
#define NBK     64            // rank buckets: bucket = rank >> 8
#define NCROSS  2016          // C(64,2) cross-bucket tasks
#define NDIAG   64            // one per bucket
#define NTASK   (NCROSS + NDIAG)

// ---------------- device scratch ----------------
__device__ __align__(16) float g_bsc[NBK * CAP];  // bucket scores (arrival order)
__device__ __align__(16) int   g_brk[NBK * CAP];  // bucket ranks  (arrival order)
__device__ __align__(16) float g_bso[NBK * CAP];  // value-sorted asc (pad +3.4e38)
__device__ __align__(16) float g_bss[NBK * CAP];  // suffix sums of sorted (pad 0)
__device__ int                 g_bcnt[NBK];
__device__ int                 g_det[NBK];        // per-block dtype votes
__device__ double              g_acc;
__device__ unsigned long long  g_tied;
__device__ unsigned            g_done;

// ---------------- K1: zero accumulators + dtype detect ----------------
// int64 (LE): odd 32-bit words of the first 64KB are high halves of values
// < 2^15 -> all zero.  int32: odd words are actual rank values (not all 0).
__global__ void k_prep(const unsigned int* __restrict__ rw) {
    int b = blockIdx.x, tid = threadIdx.x;
    int i = b * 256 + tid;
    int found = (i < NN / 2) ? (rw[2 * i + 1] != 0u) : 0;
    int any = __syncthreads_or(found);
    if (tid == 0) g_det[b] = any;
    if (i < NBK) g_bcnt[i] = 0;
    if (i == 64) g_acc  = 0.0;
    if (i == 65) g_tied = 0ull;
    if (i == 66) g_done = 0u;
}

// ---------------- K2: bucket scatter ----------------
__global__ void k_scat(const float* __restrict__ scores,
                       const unsigned int* __restrict__ rw) {
    int tid = threadIdx.x;
    int f = (tid < NBK) ? g_det[tid] : 0;
    int is32 = __syncthreads_or(f);
    int i = blockIdx.x * 256 + tid;
    int r = (int)rw[is32 ? i : 2 * i];
    if ((unsigned)r >= (unsigned)NN) r = 0;        // defensive: never IMA
    int k = r >> 8;
    int pos = atomicAdd(&g_bcnt[k], 1);
    if (pos < CAP) {
        g_bsc[k * CAP + pos] = scores[i];
        g_brk[k * CAP + pos] = r;
    }
}

// ---------------- K3: per-bucket sort (register bitonic-512) + suffix sums ----
__global__ void __launch_bounds__(CAP) k_sort() {
    __shared__ float sv[CAP];
    __shared__ float wt[16];
    int tid = threadIdx.x, b = blockIdx.x;
    int lane = tid & 31, wid = tid >> 5;
    int cnt = min(g_bcnt[b], CAP);
    float v = (tid < cnt) ? g_bsc[b * CAP + tid] : 3.402823466e38f;

    for (int k = 2; k <= CAP; k <<= 1) {
        for (int j = k >> 1; j; j >>= 1) {
            bool asc   = ((tid & k) == 0);
            bool lower = ((tid & j) == 0);
            float pv;
            if (j >= 32) {                 // cross-warp stage via smem
                __syncthreads();
                sv[tid] = v;
                __syncthreads();
                pv = sv[tid ^ j];
            } else {                       // intra-warp stage via shuffle
                pv = __shfl_xor_sync(0xffffffffu, v, j);
            }
            v = (lower == asc) ? fminf(v, pv) : fmaxf(v, pv);
        }
    }
    g_bso[b * CAP + tid] = v;

    // suffix sums (inclusive, from the right) via warp shuffles
    float x = (tid < cnt) ? v : 0.0f;
    float s = x;
#pragma unroll
    for (int o = 1; o < 32; o <<= 1) {
        float n = __shfl_down_sync(0xffffffffu, s, o);
        if (lane + o < 32) s += n;
    }
    if (lane == 0) wt[wid] = s;            // warp totals
    __syncthreads();
    if (wid == 0) {
        float t = (lane < 16) ? wt[lane] : 0.0f;
#pragma unroll
        for (int o = 1; o < 16; o <<= 1) {
            float n = __shfl_down_sync(0xffffffffu, t, o);
            if (lane + o < 32) t += n;     // zeros beyond 15 make this safe
        }
        if (lane < 16) wt[lane] = t;       // inclusive suffix of warp totals
    }
    __syncthreads();
    float after = (wid < 15) ? wt[wid + 1] : 0.0f;
    g_bss[b * CAP + tid] = s + after;
}

// ---------------- K4: cross (analytic) + diag (brute, directed) + finalize ----
__global__ void __launch_bounds__(256) k_main(float* __restrict__ out) {
    __shared__ float s1[CAP];
    __shared__ float s2[CAP];              // suffix sums (cross) / ranks (diag)
    __shared__ float wv[8];
    __shared__ long long wl[8];
    int tid = threadIdx.x;
    int t = blockIdx.x;
    float facc = 0.0f;
    long long ltied = 0;

    if (t < NCROSS) {
        // decode t -> (rB < cB); off(r) = r*(127-r)/2
        int r0 = (int)((127.0 - sqrt(16129.0 - 8.0 * (double)t)) * 0.5);
        if (r0 < 0) r0 = 0; if (r0 > 62) r0 = 62;
        while (r0 < 62 && (r0 + 1) * (127 - (r0 + 1)) / 2 <= t) r0++;
        while (r0 > 0 && r0 * (127 - r0) / 2 > t) r0--;
        int rB = r0;
        int cB = r0 + 1 + (t - r0 * (127 - r0) / 2);

        for (int u = tid; u < CAP; u += 256) {
            s1[u] = g_bso[cB * CAP + u];
            s2[u] = g_bss[cB * CAP + u];
        }
        __syncthreads();
        int cntc = min(g_bcnt[cB], CAP);
        int cntr = min(g_bcnt[rB], CAP);
        for (int i2 = tid; i2 < cntr; i2 += 256) {
            float ap = 1.0f - g_bsc[rB * CAP + i2];
            float tv = -ap;
            int pos = 0;                   // count of sorted col elems <= tv
#pragma unroll
            for (int st = 512; st; st >>= 1) {
                int np = pos + st;
                if (np <= CAP && s1[np - 1] <= tv) pos = np;
            }
            float suf = (pos < CAP) ? s2[pos] : 0.0f;
            facc += fmaf((float)(cntc - pos), ap, suf);
        }
    } else {
        int db = t - NCROSS;
        int cnt = min(g_bcnt[db], CAP);
        int* rk = (int*)s2;
        for (int u = tid; u < CAP; u += 256) {
            s1[u] = g_bsc[db * CAP + u];
            rk[u] = g_brk[db * CAP + u];
        }
        __syncthreads();
        for (int i2 = tid; i2 < cnt; i2 += 256) {
            float api = 1.0f - s1[i2];
            int ri = rk[i2];
            for (int j = 0; j < cnt; j++) {
                int rj = rk[j];
                if (rj > ri)                  facc += fmaxf(api + s1[j], 0.0f);
                else if (rj == ri && j > i2)  ltied++;
            }
        }
    }

    // block reduce -> one double atomic per block; last block finalizes
#pragma unroll
    for (int o = 16; o; o >>= 1) {
        facc  += __shfl_down_sync(0xffffffffu, facc, o);
        ltied += __shfl_down_sync(0xffffffffu, ltied, o);
    }
    int lane = tid & 31, wid = tid >> 5;
    if (lane == 0) { wv[wid] = facc; wl[wid] = ltied; }
    __syncthreads();
    if (tid == 0) {
        float sf = 0.0f; long long sl = 0;
#pragma unroll
        for (int u = 0; u < 8; u++) { sf += wv[u]; sl += wl[u]; }
        atomicAdd(&g_acc, (double)sf);
        if (sl) atomicAdd(&g_tied, (unsigned long long)sl);
        __threadfence();
        unsigned d = atomicAdd(&g_done, 1u);
        if (d == (unsigned)(NTASK - 1)) {
            double np = (double)(134209536ll - (long long)g_tied); // C(16384,2)-tied
            out[0] = (np > 0.0) ? (float)(g_acc / np) : 0.0f;
        }
    }
}

// ---------------- launch: 4 kernels ----------------
extern "C" void kernel_launch(void* const* d_in, const int* in_sizes, int n_in,
                              void* d_out, int out_size) {
    const float*        scores = (const float*)d_in[0];
    const unsigned int* ranks  = (const unsigned int*)d_in[1];
    float* out = (float*)d_out;

    k_prep<<<NBK, 256>>>(ranks);
    k_scat<<<NBK, 256>>>(scores, ranks);
    k_sort<<<NBK, CAP>>>();
    k_main<<<NTASK, 256>>>(out);
}

// round 8
// speedup vs baseline: 1.1889x; 1.0787x over previous
#include <cuda_runtime.h>
#include <cuda_bf16.h>

#define NN      16384
#define CAP     512           // per-bucket capacity (mean 256, sd 16)
#define NBK     64            // rank buckets: bucket = rank >> 8
#define NCROSS  2016          // C(64,2) cross-bucket tasks
#define NDIAG   64            // one per bucket
#define NTASK   (NCROSS + NDIAG)
#define NSLOT   32            // spread accumulator slots

// ---------------- device scratch (zero-init at load; each launch re-zeroes) ----
__device__ __align__(16) float g_bsc[NBK * CAP];  // bucket scores (arrival order)
__device__ __align__(16) int   g_brk[NBK * CAP];  // bucket ranks  (arrival order)
__device__ __align__(16) float g_bso[NBK * CAP];  // value-sorted asc (pad +3.4e38)
__device__ __align__(16) float g_bss[NBK * CAP];  // suffix sums of sorted (pad 0)
__device__ int                 g_bcnt[NBK];
__device__ double              g_accp[NSLOT];
__device__ long long           g_tiedp[NSLOT];
__device__ unsigned            g_done;

// ---------------- K1: bucket scatter (self dtype detect per block) ----------
// int64 (LE): odd 32-bit words in this block's window [256b, 256b+256) are
// high halves of 128 values < 2^15 -> all zero. int32: 128 random ranks,
// essentially never all zero. Window is within the first 64KB -> in-bounds
// for both dtypes.
__global__ void k_scat(const float* __restrict__ scores,
                       const unsigned int* __restrict__ rw) {
    int tid = threadIdx.x, b = blockIdx.x;
    int found = 0;
    if (tid < 128) found = (rw[b * 256 + 2 * tid + 1] != 0u);
    int is32 = __syncthreads_or(found);
    int i = b * 256 + tid;
    int r = (int)rw[is32 ? i : 2 * i];
    if ((unsigned)r >= (unsigned)NN) r = 0;        // defensive: never IMA
    int k = r >> 8;
    int pos = atomicAdd(&g_bcnt[k], 1);
    if (pos < CAP) {
        g_bsc[k * CAP + pos] = scores[i];
        g_brk[k * CAP + pos] = r;
    }
}

// ---------------- K2: per-bucket sort (register bitonic-512) + suffix sums ----
__global__ void __launch_bounds__(CAP) k_sort() {
    __shared__ float sv[CAP];
    __shared__ float wt[16];
    int tid = threadIdx.x, b = blockIdx.x;
    int lane = tid & 31, wid = tid >> 5;
    int cnt = min(g_bcnt[b], CAP);
    float v = (tid < cnt) ? g_bsc[b * CAP + tid] : 3.402823466e38f;

    for (int k = 2; k <= CAP; k <<= 1) {
        for (int j = k >> 1; j; j >>= 1) {
            bool asc   = ((tid & k) == 0);
            bool lower = ((tid & j) == 0);
            float pv;
            if (j >= 32) {                 // cross-warp stage via smem
                __syncthreads();
                sv[tid] = v;
                __syncthreads();
                pv = sv[tid ^ j];
            } else {                       // intra-warp stage via shuffle
                pv = __shfl_xor_sync(0xffffffffu, v, j);
            }
            v = (lower == asc) ? fminf(v, pv) : fmaxf(v, pv);
        }
    }
    g_bso[b * CAP + tid] = v;

    // inclusive suffix sums via warp shuffles
    float s = (tid < cnt) ? v : 0.0f;
#pragma unroll
    for (int o = 1; o < 32; o <<= 1) {
        float n = __shfl_down_sync(0xffffffffu, s, o);
        if (lane + o < 32) s += n;
    }
    if (lane == 0) wt[wid] = s;            // warp totals
    __syncthreads();
    if (wid == 0) {
        float t = (lane < 16) ? wt[lane] : 0.0f;
#pragma unroll
        for (int o = 1; o < 16; o <<= 1) {
            float n = __shfl_down_sync(0xffffffffu, t, o);
            if (lane + o < 32) t += n;
        }
        if (lane < 16) wt[lane] = t;       // suffix of warp totals
    }
    __syncthreads();
    float after = (wid < 15) ? wt[wid + 1] : 0.0f;
    g_bss[b * CAP + tid] = s + after;
}

// ---------------- K3: cross (analytic) + diag (brute) + finalize + re-zero ----
__global__ void __launch_bounds__(256) k_main(float* __restrict__ out) {
    __shared__ float s1[CAP];
    __shared__ float s2[CAP];              // suffix sums (cross) / ranks (diag)
    __shared__ float wv[8];
    __shared__ long long wl[8];
    int tid = threadIdx.x;
    int t = blockIdx.x;
    float facc = 0.0f;
    long long ltied = 0;

    if (t < NCROSS) {
        // decode t -> (rB < cB); off(r) = r*(127-r)/2.  Pure fp32/int.
        float disc = (float)(16129 - 8 * t);
        int r0 = (int)((127.0f - sqrtf(disc)) * 0.5f);
        if (r0 < 0) r0 = 0; if (r0 > 62) r0 = 62;
        while (r0 < 62 && (r0 + 1) * (127 - (r0 + 1)) / 2 <= t) r0++;
        while (r0 > 0 && r0 * (127 - r0) / 2 > t) r0--;
        int rB = r0;
        int cB = r0 + 1 + (t - r0 * (127 - r0) / 2);

        int cntc = min(g_bcnt[cB], CAP);
        int cntr = min(g_bcnt[rB], CAP);
        for (int u = tid; u < CAP; u += 256) {   // only real entries hit GMEM
            bool real = (u < cntc);
            s1[u] = real ? g_bso[cB * CAP + u] : 3.402823466e38f;
            s2[u] = real ? g_bss[cB * CAP + u] : 0.0f;
        }
        __syncthreads();
        for (int i2 = tid; i2 < cntr; i2 += 256) {
            float ap = 1.0f - g_bsc[rB * CAP + i2];
            float tv = -ap;
            int pos = 0;                   // count of sorted col elems <= tv
#pragma unroll
            for (int st = 512; st; st >>= 1) {
                int np = pos + st;
                if (np <= CAP && s1[np - 1] <= tv) pos = np;
            }
            float suf = (pos < CAP) ? s2[pos] : 0.0f;
            facc += fmaf((float)(cntc - pos), ap, suf);
        }
    } else {
        int db = t - NCROSS;
        int cnt = min(g_bcnt[db], CAP);
        int* rk = (int*)s2;
        for (int u = tid; u < CAP; u += 256) {
            s1[u] = g_bsc[db * CAP + u];
            rk[u] = g_brk[db * CAP + u];
        }
        __syncthreads();
        for (int i2 = tid; i2 < cnt; i2 += 256) {
            float api = 1.0f - s1[i2];
            int ri = rk[i2];
            for (int j = 0; j < cnt; j++) {
                int rj = rk[j];
                if (rj > ri)                  facc += fmaxf(api + s1[j], 0.0f);
                else if (rj == ri && j > i2)  ltied++;
            }
        }
    }

    // block reduce -> one double atomic per block (spread over NSLOT slots)
#pragma unroll
    for (int o = 16; o; o >>= 1) {
        facc  += __shfl_down_sync(0xffffffffu, facc, o);
        ltied += __shfl_down_sync(0xffffffffu, ltied, o);
    }
    int lane = tid & 31, wid = tid >> 5;
    if (lane == 0) { wv[wid] = facc; wl[wid] = ltied; }
    __syncthreads();
    if (tid == 0) {
        float sf = 0.0f; long long sl = 0;
#pragma unroll
        for (int u = 0; u < 8; u++) { sf += wv[u]; sl += wl[u]; }
        int slot = t & (NSLOT - 1);
        atomicAdd(&g_accp[slot], (double)sf);
        if (sl) atomicAdd((unsigned long long*)&g_tiedp[slot],
                          (unsigned long long)sl);
        __threadfence();
        unsigned d = atomicAdd(&g_done, 1u);
        if (d == (unsigned)(NTASK - 1)) {
            double s = 0.0; long long tt = 0;
#pragma unroll
            for (int u = 0; u < NSLOT; u++) { s += g_accp[u]; tt += g_tiedp[u]; }
            double np = (double)(134209536ll - tt);   // C(16384,2) - tied
            out[0] = (np > 0.0) ? (float)(s / np) : 0.0f;
            // re-zero all state for the next graph replay
#pragma unroll
            for (int u = 0; u < NSLOT; u++) { g_accp[u] = 0.0; g_tiedp[u] = 0; }
            for (int u = 0; u < NBK; u++) g_bcnt[u] = 0;
            g_done = 0u;
        }
    }
}

// ---------------- launch: 3 kernels ----------------
extern "C" void kernel_launch(void* const* d_in, const int* in_sizes, int n_in,
                              void* d_out, int out_size) {
    const float*        scores = (const float*)d_in[0];
    const unsigned int* ranks  = (const unsigned int*)d_in[1];
    float* out = (float*)d_out;

    k_scat<<<NBK, 256>>>(scores, ranks);
    k_sort<<<NBK, CAP>>>();
    k_main<<<NTASK, 256>>>(out);
}

// round 10
// speedup vs baseline: 1.2388x; 1.0420x over previous
#include <cuda_runtime.h>
#include <cuda_bf16.h>

#define NN      16384
#define CAP     512           // per-bucket capacity (mean 256, sd 16)
#define NBK     64            // rank buckets: bucket = rank >> 8
#define NCROSS  2016          // C(64,2) cross-bucket tasks
#define NDIAG   64            // one per bucket
#define NTASK   (NCROSS + NDIAG)
#define NSLOT   32            // spread accumulator slots
#define PADI    32            // ints per 128B line  (counter stride)
#define PADD    16            // doubles per 128B line (accumulator stride)

// ---------------- device scratch (zero-init at load; each launch re-zeroes) ----
__device__ __align__(16) float g_bsc[NBK * CAP];   // bucket scores (arrival order)
__device__ __align__(16) int   g_brk[NBK * CAP];   // bucket ranks  (arrival order)
__device__ __align__(16) float g_bso[NBK * CAP];   // value-sorted asc (pad +3.4e38)
__device__ __align__(16) float g_bss[NBK * CAP];   // suffix sums of sorted (pad 0)
__device__ __align__(128) int  g_bcnt[NBK * PADI]; // padded: one counter per 128B line
__device__ __align__(128) double    g_accp[NSLOT * PADD];
__device__ __align__(128) long long g_tiedp[NSLOT * PADD];
__device__ unsigned            g_done;

// ---------------- K1: bucket scatter (two-level, padded counters) ----------
// dtype self-detect per block: int64 (LE) -> odd 32-bit words in this block's
// window are high halves of values < 2^15 -> all zero. int32 -> actual ranks.
__global__ void k_scat(const float* __restrict__ scores,
                       const unsigned int* __restrict__ rw) {
    __shared__ int hcnt[NBK];
    __shared__ int hbase[NBK];
    int tid = threadIdx.x, b = blockIdx.x;
    if (tid < NBK) hcnt[tid] = 0;
    int found = 0;
    if (tid < 128) found = (rw[b * 256 + 2 * tid + 1] != 0u);
    int is32 = __syncthreads_or(found);          // also orders hcnt zeroing

    int i = b * 256 + tid;
    int r = (int)rw[is32 ? i : 2 * i];
    if ((unsigned)r >= (unsigned)NN) r = 0;      // defensive: never IMA
    int k = r >> 8;
    int lpos = atomicAdd(&hcnt[k], 1);           // smem atomic (cheap)
    __syncthreads();
    if (tid < NBK)
        hbase[tid] = atomicAdd(&g_bcnt[tid * PADI], hcnt[tid]); // 64 spread atomics
    __syncthreads();
    int pos = hbase[k] + lpos;
    if (pos < CAP) {
        g_bsc[k * CAP + pos] = scores[i];
        g_brk[k * CAP + pos] = r;
    }
}

// ---------------- K2: per-bucket sort (register bitonic-512) + suffix sums ----
__global__ void __launch_bounds__(CAP) k_sort() {
    __shared__ float sv[CAP];
    __shared__ float wt[16];
    int tid = threadIdx.x, b = blockIdx.x;
    int lane = tid & 31, wid = tid >> 5;
    int cnt = min(g_bcnt[b * PADI], CAP);
    float v = (tid < cnt) ? g_bsc[b * CAP + tid] : 3.402823466e38f;

    for (int k = 2; k <= CAP; k <<= 1) {
        for (int j = k >> 1; j; j >>= 1) {
            bool asc   = ((tid & k) == 0);
            bool lower = ((tid & j) == 0);
            float pv;
            if (j >= 32) {                 // cross-warp stage via smem
                __syncthreads();
                sv[tid] = v;
                __syncthreads();
                pv = sv[tid ^ j];
            } else {                       // intra-warp stage via shuffle
                pv = __shfl_xor_sync(0xffffffffu, v, j);
            }
            v = (lower == asc) ? fminf(v, pv) : fmaxf(v, pv);
        }
    }
    g_bso[b * CAP + tid] = v;

    // inclusive suffix sums via warp shuffles
    float s = (tid < cnt) ? v : 0.0f;
#pragma unroll
    for (int o = 1; o < 32; o <<= 1) {
        float n = __shfl_down_sync(0xffffffffu, s, o);
        if (lane + o < 32) s += n;
    }
    if (lane == 0) wt[wid] = s;            // warp totals
    __syncthreads();
    if (wid == 0) {
        float t = (lane < 16) ? wt[lane] : 0.0f;
#pragma unroll
        for (int o = 1; o < 16; o <<= 1) {
            float n = __shfl_down_sync(0xffffffffu, t, o);
            if (lane + o < 32) t += n;
        }
        if (lane < 16) wt[lane] = t;       // suffix of warp totals
    }
    __syncthreads();
    float after = (wid < 15) ? wt[wid + 1] : 0.0f;
    g_bss[b * CAP + tid] = s + after;
}

// ---------------- K3: cross (analytic) + diag (brute) + finalize + re-zero ----
__global__ void __launch_bounds__(256) k_main(float* __restrict__ out) {
    __shared__ float s1[CAP];
    __shared__ float s2[CAP];              // suffix sums (cross) / ranks (diag)
    __shared__ float wv[8];
    __shared__ long long wl[8];
    int tid = threadIdx.x;
    int t = blockIdx.x;
    float facc = 0.0f;
    long long ltied = 0;

    if (t < NCROSS) {
        // decode t -> (rB < cB); off(r) = r*(127-r)/2.  Pure fp32/int.
        float disc = (float)(16129 - 8 * t);
        int r0 = (int)((127.0f - sqrtf(disc)) * 0.5f);
        if (r0 < 0) r0 = 0; if (r0 > 62) r0 = 62;
        while (r0 < 62 && (r0 + 1) * (127 - (r0 + 1)) / 2 <= t) r0++;
        while (r0 > 0 && r0 * (127 - r0) / 2 > t) r0--;
        int rB = r0;
        int cB = r0 + 1 + (t - r0 * (127 - r0) / 2);

        int cntc = min(g_bcnt[cB * PADI], CAP);
        int cntr = min(g_bcnt[rB * PADI], CAP);
        for (int u = tid; u < CAP; u += 256) {   // only real entries hit GMEM
            bool real = (u < cntc);
            s1[u] = real ? g_bso[cB * CAP + u] : 3.402823466e38f;
            s2[u] = real ? g_bss[cB * CAP + u] : 0.0f;
        }
        __syncthreads();
        for (int i2 = tid; i2 < cntr; i2 += 256) {
            float ap = 1.0f - g_bsc[rB * CAP + i2];
            float tv = -ap;
            int pos = 0;                   // count of sorted col elems <= tv
#pragma unroll
            for (int st = 512; st; st >>= 1) {
                int np = pos + st;
                if (np <= CAP && s1[np - 1] <= tv) pos = np;
            }
            float suf = (pos < CAP) ? s2[pos] : 0.0f;
            facc += fmaf((float)(cntc - pos), ap, suf);
        }
    } else {
        int db = t - NCROSS;
        int cnt = min(g_bcnt[db * PADI], CAP);
        int* rk = (int*)s2;
        for (int u = tid; u < CAP; u += 256) {
            s1[u] = g_bsc[db * CAP + u];
            rk[u] = g_brk[db * CAP + u];
        }
        __syncthreads();
        for (int i2 = tid; i2 < cnt; i2 += 256) {
            float api = 1.0f - s1[i2];
            int ri = rk[i2];
            for (int j = 0; j < cnt; j++) {
                int rj = rk[j];
                if (rj > ri)                  facc += fmaxf(api + s1[j], 0.0f);
                else if (rj == ri && j > i2)  ltied++;
            }
        }
    }

    // block reduce -> one double atomic per block, 128B-strided slots
#pragma unroll
    for (int o = 16; o; o >>= 1) {
        facc  += __shfl_down_sync(0xffffffffu, facc, o);
        ltied += __shfl_down_sync(0xffffffffu, ltied, o);
    }
    int lane = tid & 31, wid = tid >> 5;
    if (lane == 0) { wv[wid] = facc; wl[wid] = ltied; }
    __syncthreads();
    if (tid == 0) {
        float sf = 0.0f; long long sl = 0;
#pragma unroll
        for (int u = 0; u < 8; u++) { sf += wv[u]; sl += wl[u]; }
        int slot = (t & (NSLOT - 1)) * PADD;
        atomicAdd(&g_accp[slot], (double)sf);
        if (sl) atomicAdd((unsigned long long*)&g_tiedp[slot],
                          (unsigned long long)sl);
        __threadfence();
        unsigned d = atomicAdd(&g_done, 1u);
        if (d == (unsigned)(NTASK - 1)) {
            double s = 0.0; long long tt = 0;
#pragma unroll
            for (int u = 0; u < NSLOT; u++) {
                s  += g_accp[u * PADD];
                tt += g_tiedp[u * PADD];
            }
            double np = (double)(134209536ll - tt);   // C(16384,2) - tied
            out[0] = (np > 0.0) ? (float)(s / np) : 0.0f;
            // re-zero all state for the next graph replay
#pragma unroll
            for (int u = 0; u < NSLOT; u++) {
                g_accp[u * PADD] = 0.0;
                g_tiedp[u * PADD] = 0;
            }
            for (int u = 0; u < NBK; u++) g_bcnt[u * PADI] = 0;
            g_done = 0u;
        }
    }
}

// ---------------- launch: 3 kernels ----------------
extern "C" void kernel_launch(void* const* d_in, const int* in_sizes, int n_in,
                              void* d_out, int out_size) {
    const float*        scores = (const float*)d_in[0];
    const unsigned int* ranks  = (const unsigned int*)d_in[1];
    float* out = (float*)d_out;

    k_scat<<<NBK, 256>>>(scores, ranks);
    k_sort<<<NBK, CAP>>>();
    k_main<<<NTASK, 256>>>(out);
}

// round 11
// speedup vs baseline: 2.2320x; 1.8017x over previous
#include <cuda_runtime.h>
#include <cuda_bf16.h>

#define NN      16384
#define CAP     512           // per-bucket capacity (mean 256, sd 16)
#define NBK     64            // rank buckets: bucket = rank >> 8
#define GY      9             // 8 cross row-chunks + 1 diag
#define NBLK    (NBK * GY)    // 576 k_main blocks
#define NSLOT   32            // spread accumulator slots
#define PADI    32            // ints per 128B line  (counter stride)
#define PADD    16            // doubles per 128B line (accumulator stride)

// ---------------- device scratch (zero-init at load; each launch re-zeroes) ----
__device__ __align__(16) float g_bsc[NBK * CAP];   // bucket scores (arrival order)
__device__ __align__(16) int   g_brk[NBK * CAP];   // bucket ranks  (arrival order)
__device__ __align__(16) float g_bso[NBK * CAP];   // value-sorted asc (pad +3.4e38)
__device__ __align__(16) float g_bss[NBK * CAP];   // suffix sums of sorted (pad 0)
__device__ __align__(128) int  g_bcnt[NBK * PADI]; // one counter per 128B line
__device__ __align__(128) double    g_accp[NSLOT * PADD];
__device__ __align__(128) long long g_tiedp[NSLOT * PADD];
__device__ unsigned            g_done;

// ---------------- K1: bucket scatter (two-level, padded counters) ----------
// dtype self-detect per block: int64 (LE) -> odd 32-bit words in this block's
// window are high halves of values < 2^15 -> all zero. int32 -> actual ranks.
__global__ void k_scat(const float* __restrict__ scores,
                       const unsigned int* __restrict__ rw) {
    __shared__ int hcnt[NBK];
    __shared__ int hbase[NBK];
    int tid = threadIdx.x, b = blockIdx.x;
    int i = b * 256 + tid;
    float sv = scores[i];                        // overlap with detect chain
    if (tid < NBK) hcnt[tid] = 0;
    int found = 0;
    if (tid < 128) found = (rw[b * 256 + 2 * tid + 1] != 0u);
    int is32 = __syncthreads_or(found);          // also orders hcnt zeroing

    int r = (int)rw[is32 ? i : 2 * i];
    if ((unsigned)r >= (unsigned)NN) r = 0;      // defensive: never IMA
    int k = r >> 8;
    int lpos = atomicAdd(&hcnt[k], 1);           // smem atomic (cheap)
    __syncthreads();
    if (tid < NBK)
        hbase[tid] = atomicAdd(&g_bcnt[tid * PADI], hcnt[tid]); // 64 spread atomics
    __syncthreads();
    int pos = hbase[k] + lpos;
    if (pos < CAP) {
        g_bsc[k * CAP + pos] = sv;
        g_brk[k * CAP + pos] = r;
    }
}

// ---------------- K2: per-bucket sort (register bitonic-512) + suffix sums ----
__global__ void __launch_bounds__(CAP) k_sort() {
    __shared__ float sv[CAP];
    __shared__ float wt[16];
    int tid = threadIdx.x, b = blockIdx.x;
    int lane = tid & 31, wid = tid >> 5;
    int cnt = min(g_bcnt[b * PADI], CAP);
    float v = (tid < cnt) ? g_bsc[b * CAP + tid] : 3.402823466e38f;

    for (int k = 2; k <= CAP; k <<= 1) {
        for (int j = k >> 1; j; j >>= 1) {
            bool asc   = ((tid & k) == 0);
            bool lower = ((tid & j) == 0);
            float pv;
            if (j >= 32) {                 // cross-warp stage via smem
                __syncthreads();
                sv[tid] = v;
                __syncthreads();
                pv = sv[tid ^ j];
            } else {                       // intra-warp stage via shuffle
                pv = __shfl_xor_sync(0xffffffffu, v, j);
            }
            v = (lower == asc) ? fminf(v, pv) : fmaxf(v, pv);
        }
    }
    g_bso[b * CAP + tid] = v;

    // inclusive suffix sums via warp shuffles
    float s = (tid < cnt) ? v : 0.0f;
#pragma unroll
    for (int o = 1; o < 32; o <<= 1) {
        float n = __shfl_down_sync(0xffffffffu, s, o);
        if (lane + o < 32) s += n;
    }
    if (lane == 0) wt[wid] = s;            // warp totals
    __syncthreads();
    if (wid == 0) {
        float t = (lane < 16) ? wt[lane] : 0.0f;
#pragma unroll
        for (int o = 1; o < 16; o <<= 1) {
            float n = __shfl_down_sync(0xffffffffu, t, o);
            if (lane + o < 32) t += n;
        }
        if (lane < 16) wt[lane] = t;       // suffix of warp totals
    }
    __syncthreads();
    float after = (wid < 15) ? wt[wid + 1] : 0.0f;
    g_bss[b * CAP + tid] = s + after;
}

// ---------------- K3: column-reuse cross + diag + finalize + re-zero ----------
// grid (64, 9): block (c, y<8) serves row buckets [8y,8y+8) cap c against
// column bucket c (loaded once). block (c, 8) = diag of bucket c.
__global__ void __launch_bounds__(256) k_main(float* __restrict__ out) {
    __shared__ float s1[CAP];
    __shared__ float s2[CAP];              // suffix sums (cross) / ranks (diag)
    __shared__ float wv[8];
    __shared__ long long wl[8];
    const int tid = threadIdx.x;
    const int c = blockIdx.x, y = blockIdx.y;
    float facc = 0.0f;
    long long ltied = 0;

    if (y < 8) {
        int rlo = y * 8;
        int rhi = min(rlo + 8, c);
        if (rlo < rhi) {                   // uniform per block
            int cntc = min(g_bcnt[c * PADI], CAP);
            for (int u = tid; u < CAP; u += 256) {
                bool real = (u < cntc);
                s1[u] = real ? g_bso[c * CAP + u] : 3.402823466e38f;
                s2[u] = real ? g_bss[c * CAP + u] : 0.0f;
            }
            __syncthreads();
            float fcntc = (float)cntc;
            for (int rb = rlo; rb < rhi; rb++) {
                int cntr = min(g_bcnt[rb * PADI], CAP);
                for (int i2 = tid; i2 < cntr; i2 += 256) {
                    float ap = 1.0f - g_bsc[rb * CAP + i2];
                    float tv = -ap;
                    int pos = 0;           // count of sorted col elems <= tv
#pragma unroll
                    for (int st = 512; st; st >>= 1) {
                        int np = pos + st;
                        if (np <= CAP && s1[np - 1] <= tv) pos = np;
                    }
                    float suf = (pos < CAP) ? s2[pos] : 0.0f;
                    facc += fmaf(fcntc - (float)pos, ap, suf);
                }
            }
        }
    } else {
        int cnt = min(g_bcnt[c * PADI], CAP);
        int* rk = (int*)s2;
        for (int u = tid; u < CAP; u += 256) {
            s1[u] = g_bsc[c * CAP + u];
            rk[u] = g_brk[c * CAP + u];
        }
        __syncthreads();
        for (int i2 = tid; i2 < cnt; i2 += 256) {
            float api = 1.0f - s1[i2];
            int ri = rk[i2];
            for (int j = 0; j < cnt; j++) {
                int rj = rk[j];
                if (rj > ri)                  facc += fmaxf(api + s1[j], 0.0f);
                else if (rj == ri && j > i2)  ltied++;
            }
        }
    }

    // block reduce -> one double atomic per block, 128B-strided slots.
    // ALL blocks (even empty ones) reach here so g_done completes.
#pragma unroll
    for (int o = 16; o; o >>= 1) {
        facc  += __shfl_down_sync(0xffffffffu, facc, o);
        ltied += __shfl_down_sync(0xffffffffu, ltied, o);
    }
    int lane = tid & 31, wid = tid >> 5;
    if (lane == 0) { wv[wid] = facc; wl[wid] = ltied; }
    __syncthreads();
    if (tid == 0) {
        float sf = 0.0f; long long sl = 0;
#pragma unroll
        for (int u = 0; u < 8; u++) { sf += wv[u]; sl += wl[u]; }
        int slot = ((c + y) & (NSLOT - 1)) * PADD;
        atomicAdd(&g_accp[slot], (double)sf);
        if (sl) atomicAdd((unsigned long long*)&g_tiedp[slot],
                          (unsigned long long)sl);
        __threadfence();
        unsigned d = atomicAdd(&g_done, 1u);
        if (d == (unsigned)(NBLK - 1)) {
            double s = 0.0; long long tt = 0;
#pragma unroll
            for (int u = 0; u < NSLOT; u++) {
                s  += g_accp[u * PADD];
                tt += g_tiedp[u * PADD];
            }
            double np = (double)(134209536ll - tt);   // C(16384,2) - tied
            out[0] = (np > 0.0) ? (float)(s / np) : 0.0f;
            // re-zero all state for the next graph replay
#pragma unroll
            for (int u = 0; u < NSLOT; u++) {
                g_accp[u * PADD] = 0.0;
                g_tiedp[u * PADD] = 0;
            }
            for (int u = 0; u < NBK; u++) g_bcnt[u * PADI] = 0;
            g_done = 0u;
        }
    }
}

// ---------------- launch: 3 kernels ----------------
extern "C" void kernel_launch(void* const* d_in, const int* in_sizes, int n_in,
                              void* d_out, int out_size) {
    const float*        scores = (const float*)d_in[0];
    const unsigned int* ranks  = (const unsigned int*)d_in[1];
    float* out = (float*)d_out;

    k_scat<<<NBK, 256>>>(scores, ranks);
    k_sort<<<NBK, CAP>>>();
    k_main<<<dim3(NBK, GY), 256>>>(out);
}